// round 15
// baseline (speedup 1.0000x reference)
#include <cuda_runtime.h>
#include <cuda_fp16.h>
#include <cstdint>

// ---------------------------------------------------------------------------
// Problem constants
// ---------------------------------------------------------------------------
#define D_IN   4096
#define D_OUT  4096
#define M_TOT  8192
#define NEXP   8
#define RANK   4
#define P32    32

// ---------------------------------------------------------------------------
// Device scratch (static; no cudaMalloc allowed)
// ---------------------------------------------------------------------------
__device__ __half g_xh[(size_t)M_TOT * D_IN];   // fp16 of x
__device__ __half g_bh[(size_t)D_OUT * D_IN];   // fp16 of base_w
__device__ __half g_dh[(size_t)P32 * D_IN];     // fp16 of down_w (as [32, 4096])
__device__ __half g_tA[(size_t)M_TOT * 64];     // [th(32) | tl(32)] * 2*rw
__device__ __half g_uB[(size_t)D_OUT * 64];     // [uh(32) | uh(32)]

// ---------------------------------------------------------------------------
// Helpers
// ---------------------------------------------------------------------------
__device__ __forceinline__ uint32_t smem_u32(const void* p) {
    uint32_t a;
    asm("{ .reg .u64 t; cvta.to.shared.u64 t, %1; cvt.u32.u64 %0, t; }"
        : "=r"(a) : "l"(p));
    return a;
}
#define CP_ASYNC16(so, g) \
    asm volatile("cp.async.cg.shared.global [%0], [%1], 16;" :: "r"(so), "l"(g))
#define CP_COMMIT() asm volatile("cp.async.commit_group;" ::: "memory")
#define CP_WAIT1()  asm volatile("cp.async.wait_group 1;" ::: "memory")
#define CP_WAIT2()  asm volatile("cp.async.wait_group 2;" ::: "memory")

#define LDSM_X4(r0, r1, r2, r3, addr)                                          \
    asm volatile("ldmatrix.sync.aligned.m8n8.x4.shared.b16 {%0,%1,%2,%3}, [%4];"\
                 : "=r"(r0), "=r"(r1), "=r"(r2), "=r"(r3) : "r"(addr))

#define MMA_16816(c, a, b)                                                     \
    asm volatile("mma.sync.aligned.m16n8k16.row.col.f32.f16.f16.f32 "          \
                 "{%0,%1,%2,%3}, {%4,%5,%6,%7}, {%8,%9}, {%0,%1,%2,%3};"       \
                 : "+f"((c)[0]), "+f"((c)[1]), "+f"((c)[2]), "+f"((c)[3])      \
                 : "r"((a)[0]), "r"((a)[1]), "r"((a)[2]), "r"((a)[3]),         \
                   "r"((b)[0]), "r"((b)[1]))

// ---------------------------------------------------------------------------
// Streaming fp32 -> fp16 conversion (8 elems / thread)
// ---------------------------------------------------------------------------
__device__ __forceinline__ void conv8(const float* __restrict__ s,
                                      __half* __restrict__ d, size_t i) {
    float4 v0 = *(const float4*)(s + i);
    float4 v1 = *(const float4*)(s + i + 4);
    *(__half2*)(d + i)     = __floats2half2_rn(v0.x, v0.y);
    *(__half2*)(d + i + 2) = __floats2half2_rn(v0.z, v0.w);
    *(__half2*)(d + i + 4) = __floats2half2_rn(v1.x, v1.y);
    *(__half2*)(d + i + 6) = __floats2half2_rn(v1.z, v1.w);
}

// Branch A: x -> g_xh, down_w -> g_dh  (feeds down_mma)
#define CA_X 16384      // 8192*4096 / (256*8)
#define CA_D 64         // 32*4096   / (256*8)
#define CA_BLKS (CA_X + CA_D)
__global__ __launch_bounds__(256)
void conv_a(const float* __restrict__ x, const float* __restrict__ down_w) {
    const int blk = blockIdx.x;
    const int tid = threadIdx.x;
    if (blk < CA_X) conv8(x, g_xh, ((size_t)blk * 256 + tid) * 8);
    else            conv8(down_w, g_dh, ((size_t)(blk - CA_X) * 256 + tid) * 8);
}

// Branch B: base_w -> g_bh, uB prep  (feeds only the main GEMM)
#define CB_B 8192       // 4096*4096 / (256*8)
#define CB_U 512        // 4096*32   / 256
#define CB_BLKS (CB_B + CB_U)
__global__ __launch_bounds__(256)
void conv_b(const float* __restrict__ base_w, const float* __restrict__ up_w) {
    const int blk = blockIdx.x;
    const int tid = threadIdx.x;
    if (blk < CB_B) {
        conv8(base_w, g_bh, ((size_t)blk * 256 + tid) * 8);
    } else {
        int idx = (blk - CB_B) * 256 + tid;
        int n = idx >> 5, p = idx & 31;
        int e = p >> 2, r = p & 3;
        __half uh = __float2half(up_w[((size_t)e * D_OUT + n) * RANK + r]);
        __half* row = g_uB + (size_t)n * 64;
        row[p] = uh; row[32 + p] = uh;
    }
}

// ---------------------------------------------------------------------------
// down_mma: t = xh . dh^T  (M=8192, N=32, K=4096) on tensor cores, with the
// adapter-A (tA hi/lo * 2*rw) epilogue fused in.  (unchanged from R13)
// ---------------------------------------------------------------------------
#define DBM 128
#define DRST 144
#define D_A_BYTES (DBM * DRST)           // 18432
#define D_B_BYTES (P32 * DRST)           // 4608
#define D_STAGE (D_A_BYTES + D_B_BYTES)  // 23040
#define D_NSTG 3
#define D_SMEM (D_NSTG * D_STAGE)        // 69120
#define D_NST 64

__device__ __forceinline__ void load_dstage(int s, int buf, int m0, int tid,
                                            uint32_t smbase) {
    const int k0 = s * 64;
    const uint32_t sb = smbase + buf * D_STAGE;
#pragma unroll
    for (int j = 0; j < 8; j++) {
        int c = j * 128 + tid;
        int row = c >> 3, ch = c & 7;
        const __half* g = g_xh + (size_t)(m0 + row) * D_IN + k0 + ch * 8;
        CP_ASYNC16(sb + row * DRST + ch * 16, g);
    }
#pragma unroll
    for (int j = 0; j < 2; j++) {
        int c = j * 128 + tid;
        int row = c >> 3, ch = c & 7;
        const __half* g = g_dh + (size_t)row * D_IN + k0 + ch * 8;
        CP_ASYNC16(sb + D_A_BYTES + row * DRST + ch * 16, g);
    }
}

__global__ __launch_bounds__(128)
void down_mma(const float* __restrict__ rw) {
    extern __shared__ char smem[];
    const uint32_t smbase = smem_u32(smem);
    const int tid  = threadIdx.x;
    const int wid  = tid >> 5;
    const int lane = tid & 31;
    const int m0   = blockIdx.x * DBM;

    float c[2][4][4];
#pragma unroll
    for (int i = 0; i < 2; i++)
#pragma unroll
        for (int j = 0; j < 4; j++)
#pragma unroll
            for (int q = 0; q < 4; q++) c[i][j][q] = 0.0f;

    const uint32_t lm_off = (lane & 15) * DRST + (lane >> 4) * 16;
    const uint32_t a_lane = smbase + (wid * 32) * DRST + lm_off;
    const uint32_t b_lane = smbase + D_A_BYTES + lm_off;

    load_dstage(0, 0, m0, tid, smbase); CP_COMMIT();
    load_dstage(1, 1, m0, tid, smbase); CP_COMMIT();

    int buf = 0, bufp = 2;
    for (int s = 0; s < D_NST; s++) {
        CP_WAIT1();
        __syncthreads();
        if (s + 2 < D_NST)
            load_dstage(s + 2, bufp, m0, tid, smbase);
        CP_COMMIT();

        const uint32_t ab = a_lane + buf * D_STAGE;
        const uint32_t bb = b_lane + buf * D_STAGE;
#pragma unroll
        for (int ks = 0; ks < 4; ks++) {
            uint32_t a[2][4], b[4][2];
            LDSM_X4(b[0][0], b[1][0], b[0][1], b[1][1], bb + ks * 32);
            LDSM_X4(b[2][0], b[3][0], b[2][1], b[3][1], bb + 16 * DRST + ks * 32);
#pragma unroll
            for (int mi = 0; mi < 2; mi++)
                LDSM_X4(a[mi][0], a[mi][1], a[mi][2], a[mi][3],
                        ab + mi * 16 * DRST + ks * 32);
#pragma unroll
            for (int mi = 0; mi < 2; mi++)
#pragma unroll
                for (int ni = 0; ni < 4; ni++)
                    MMA_16816(c[mi][ni], a[mi], b[ni]);
        }
        buf  = (buf  == D_NSTG - 1) ? 0 : buf + 1;
        bufp = (bufp == D_NSTG - 1) ? 0 : bufp + 1;
    }

#pragma unroll
    for (int mi = 0; mi < 2; mi++) {
        const int r0 = m0 + wid * 32 + mi * 16 + (lane >> 2);
        const int b  = r0 >> 11;
#pragma unroll
        for (int ni = 0; ni < 4; ni++) {
            const int c0 = ni * 8 + 2 * (lane & 3);
            const float s2 = 2.0f * rw[b * NEXP + (c0 >> 2)];
#pragma unroll
            for (int q = 0; q < 4; q++) {
                const int m = (q < 2) ? r0 : r0 + 8;
                const int p = c0 + (q & 1);
                float v = c[mi][ni][q] * s2;
                __half th = __float2half(v);
                __half tl = __float2half(v - __half2float(th));
                g_tA[(size_t)m * 64 + p]      = th;
                g_tA[(size_t)m * 64 + 32 + p] = tl;
            }
        }
    }
}

// ---------------------------------------------------------------------------
// Persistent mma.sync GEMM (measured-best configuration, unchanged).
// ---------------------------------------------------------------------------
#define BM 128
#define BN 256
#define BK 64
#define RSTRB 144
#define A_BYTES (BM * RSTRB)             // 18432
#define B_BYTES (BN * RSTRB)             // 36864
#define STAGE_BYTES (A_BYTES + B_BYTES)  // 55296
#define NSTAGES 4
#define SMEM_DYN (NSTAGES * STAGE_BYTES) // 221184
#define NST 65
#define NTILES 1024
#define GRID_CTAS 148

__device__ __forceinline__ void tile_mn(int bid, int tl, int& m0, int& n0) {
    int t = bid + tl * GRID_CTAS;
    n0 = (t & 15) * BN;
    m0 = (t >> 4) * BM;
}

__device__ __forceinline__ void stage_params(int s, const __half*& ap,
                                             const __half*& bp,
                                             int& ld, int& k0) {
    if (s < 64) { ap = g_xh; bp = g_bh; ld = D_IN; k0 = s * BK; }
    else        { ap = g_tA; bp = g_uB; ld = 64;   k0 = 0; }
}

__device__ __forceinline__ void load_stage(int s, int buf, int m0, int n0,
                                           int tid, uint32_t smbase) {
    const __half *ap, *bp;
    int ld, k0;
    stage_params(s, ap, bp, ld, k0);
    const uint32_t sb = smbase + buf * STAGE_BYTES;
#pragma unroll
    for (int j = 0; j < 4; j++) {
        int c = j * 256 + tid;
        int row = c >> 3, ch = c & 7;
        const __half* g = ap + (size_t)(m0 + row) * ld + k0 + ch * 8;
        CP_ASYNC16(sb + row * RSTRB + ch * 16, g);
    }
#pragma unroll
    for (int j = 0; j < 8; j++) {
        int c = j * 256 + tid;
        int row = c >> 3, ch = c & 7;
        const __half* g = bp + (size_t)(n0 + row) * ld + k0 + ch * 8;
        CP_ASYNC16(sb + A_BYTES + row * RSTRB + ch * 16, g);
    }
}

__global__ __launch_bounds__(256, 1)
void gemm_mma(float* __restrict__ out) {
    extern __shared__ char smem[];
    const uint32_t smbase = smem_u32(smem);

    const int tid  = threadIdx.x;
    const int wid  = tid >> 5;
    const int lane = tid & 31;
    const int wm   = wid >> 2;
    const int wn   = wid & 3;
    const int bid  = blockIdx.x;

    const int nt_local = (NTILES - bid + GRID_CTAS - 1) / GRID_CTAS;
    const int total = nt_local * NST;

    float c[4][8][4];
#pragma unroll
    for (int i = 0; i < 4; i++)
#pragma unroll
        for (int j = 0; j < 8; j++)
#pragma unroll
            for (int q = 0; q < 4; q++) c[i][j][q] = 0.0f;

    const uint32_t lm_off = (lane & 15) * RSTRB + (lane >> 4) * 16;
    const uint32_t a_lane = smbase + (wm * 64) * RSTRB + lm_off;
    const uint32_t b_lane = smbase + A_BYTES + (wn * 64) * RSTRB + lm_off;

    int pf_s = 0, pf_tl = 0, pf_m0, pf_n0;
    tile_mn(bid, 0, pf_m0, pf_n0);
    int cur_s = 0, cur_tl = 0, cur_m0, cur_n0;
    tile_mn(bid, 0, cur_m0, cur_n0);

#pragma unroll
    for (int i = 0; i < NSTAGES - 1; i++) {
        load_stage(pf_s, i, pf_m0, pf_n0, tid, smbase);
        CP_COMMIT();
        if (++pf_s == NST) {
            pf_s = 0;
            if (++pf_tl < nt_local) tile_mn(bid, pf_tl, pf_m0, pf_n0);
        }
    }

    int buf = 0, bufp = NSTAGES - 1;
    for (int it = 0; it < total; it++) {
        CP_WAIT2();
        __syncthreads();

        if (it + NSTAGES - 1 < total) {
            load_stage(pf_s, bufp, pf_m0, pf_n0, tid, smbase);
            if (++pf_s == NST) {
                pf_s = 0;
                if (++pf_tl < nt_local) tile_mn(bid, pf_tl, pf_m0, pf_n0);
            }
        }
        CP_COMMIT();

        const uint32_t ab = a_lane + buf * STAGE_BYTES;
        const uint32_t bb = b_lane + buf * STAGE_BYTES;
#pragma unroll
        for (int ks = 0; ks < 4; ks++) {
            uint32_t a[4][4], b[8][2];
#pragma unroll
            for (int mi = 0; mi < 4; mi++)
                LDSM_X4(a[mi][0], a[mi][1], a[mi][2], a[mi][3],
                        ab + mi * 16 * RSTRB + ks * 32);
#pragma unroll
            for (int nt = 0; nt < 4; nt++)
                LDSM_X4(b[2 * nt][0], b[2 * nt + 1][0],
                        b[2 * nt][1], b[2 * nt + 1][1],
                        bb + nt * 16 * RSTRB + ks * 32);
#pragma unroll
            for (int mi = 0; mi < 4; mi++)
#pragma unroll
                for (int ni = 0; ni < 8; ni++)
                    MMA_16816(c[mi][ni], a[mi], b[ni]);
        }

        if (cur_s == NST - 1) {
            const int rbase = cur_m0 + wm * 64 + (lane >> 2);
            const int cbase = cur_n0 + wn * 64 + 2 * (lane & 3);
#pragma unroll
            for (int mi = 0; mi < 4; mi++) {
#pragma unroll
                for (int ni = 0; ni < 8; ni++) {
                    float* p0 = out + (size_t)(rbase + mi * 16) * D_OUT + cbase + ni * 8;
                    float* p1 = p0 + 8 * D_OUT;
                    *(float2*)p0 = make_float2(c[mi][ni][0], c[mi][ni][1]);
                    *(float2*)p1 = make_float2(c[mi][ni][2], c[mi][ni][3]);
                }
            }
#pragma unroll
            for (int i = 0; i < 4; i++)
#pragma unroll
                for (int j = 0; j < 8; j++)
#pragma unroll
                    for (int q = 0; q < 4; q++) c[i][j][q] = 0.0f;
            cur_s = 0;
            if (++cur_tl < nt_local) tile_mn(bid, cur_tl, cur_m0, cur_n0);
        } else {
            cur_s++;
        }

        buf  = (buf  == NSTAGES - 1) ? 0 : buf + 1;
        bufp = (bufp == NSTAGES - 1) ? 0 : bufp + 1;
    }
}

// ---------------------------------------------------------------------------
// Launch with a fork/join DAG (graph-capturable: events + side stream only).
//   stream0:  conv_a (x, down_w)  ->  down_mma  ------\
//   side:     conv_b (base_w, uB)  [parallel branch] --+-->  gemm_mma
// Inputs (metadata order): x, routing_weights, base_w, down_w, up_w
// ---------------------------------------------------------------------------
extern "C" void kernel_launch(void* const* d_in, const int* in_sizes, int n_in,
                              void* d_out, int out_size) {
    const float* x      = (const float*)d_in[0];
    const float* rw     = (const float*)d_in[1];
    const float* base_w = (const float*)d_in[2];
    const float* down_w = (const float*)d_in[3];
    const float* up_w   = (const float*)d_in[4];
    float* out = (float*)d_out;

    cudaFuncSetAttribute(gemm_mma, cudaFuncAttributeMaxDynamicSharedMemorySize,
                         SMEM_DYN);
    cudaFuncSetAttribute(down_mma, cudaFuncAttributeMaxDynamicSharedMemorySize,
                         D_SMEM);

    cudaStream_t side;
    cudaEvent_t ev_fork, ev_join;
    cudaStreamCreateWithFlags(&side, cudaStreamNonBlocking);
    cudaEventCreateWithFlags(&ev_fork, cudaEventDisableTiming);
    cudaEventCreateWithFlags(&ev_join, cudaEventDisableTiming);

    // Fork: side branch starts from the same point as branch A.
    cudaEventRecord(ev_fork, 0);
    cudaStreamWaitEvent(side, ev_fork, 0);

    conv_a<<<CA_BLKS, 256, 0, 0>>>(x, down_w);            // branch A
    conv_b<<<CB_BLKS, 256, 0, side>>>(base_w, up_w);      // branch B (parallel)
    down_mma<<<M_TOT / DBM, 128, D_SMEM, 0>>>(rw);        // after conv_a

    // Join: gemm waits on branch B too.
    cudaEventRecord(ev_join, side);
    cudaStreamWaitEvent(0, ev_join, 0);

    gemm_mma<<<GRID_CTAS, 256, SMEM_DYN, 0>>>(out);
}

// round 16
// speedup vs baseline: 1.0280x; 1.0280x over previous
#include <cuda_runtime.h>
#include <cuda_fp16.h>
#include <cstdint>

// ---------------------------------------------------------------------------
// Problem constants
// ---------------------------------------------------------------------------
#define D_IN   4096
#define D_OUT  4096
#define M_TOT  8192
#define NEXP   8
#define RANK   4
#define P32    32

// ---------------------------------------------------------------------------
// Device scratch (static; no cudaMalloc allowed)
// ---------------------------------------------------------------------------
__device__ __half g_xh[(size_t)M_TOT * D_IN];   // fp16 of x
__device__ __half g_bh[(size_t)D_OUT * D_IN];   // fp16 of base_w
__device__ __half g_dh[(size_t)P32 * D_IN];     // fp16 of down_w (as [32, 4096])
__device__ __half g_tA[(size_t)M_TOT * 128];    // [th|tl|0|0] * 2*rw (128-wide)
__device__ __half g_uB[(size_t)D_OUT * 128];    // [uh|uh|0|0]        (128-wide)

// ---------------------------------------------------------------------------
// Helpers
// ---------------------------------------------------------------------------
__device__ __forceinline__ uint32_t smem_u32(const void* p) {
    uint32_t a;
    asm("{ .reg .u64 t; cvta.to.shared.u64 t, %1; cvt.u32.u64 %0, t; }"
        : "=r"(a) : "l"(p));
    return a;
}
#define CP_ASYNC16(so, g) \
    asm volatile("cp.async.cg.shared.global [%0], [%1], 16;" :: "r"(so), "l"(g))
#define CP_COMMIT() asm volatile("cp.async.commit_group;" ::: "memory")
#define CP_WAIT0()  asm volatile("cp.async.wait_group 0;" ::: "memory")
#define CP_WAIT1()  asm volatile("cp.async.wait_group 1;" ::: "memory")

#define LDSM_X4(r0, r1, r2, r3, addr)                                          \
    asm volatile("ldmatrix.sync.aligned.m8n8.x4.shared.b16 {%0,%1,%2,%3}, [%4];"\
                 : "=r"(r0), "=r"(r1), "=r"(r2), "=r"(r3) : "r"(addr))

#define MMA_16816(c, a, b)                                                     \
    asm volatile("mma.sync.aligned.m16n8k16.row.col.f32.f16.f16.f32 "          \
                 "{%0,%1,%2,%3}, {%4,%5,%6,%7}, {%8,%9}, {%0,%1,%2,%3};"       \
                 : "+f"((c)[0]), "+f"((c)[1]), "+f"((c)[2]), "+f"((c)[3])      \
                 : "r"((a)[0]), "r"((a)[1]), "r"((a)[2]), "r"((a)[3]),         \
                   "r"((b)[0]), "r"((b)[1]))

// ---------------------------------------------------------------------------
// conv_all: ONE streaming launch, all DRAM-bound prep (serial with the rest;
// overlapping memory-bound phases was measured to regress).
// ---------------------------------------------------------------------------
#define CV_X 32768      // 8192*4096 / (128*8)
#define CV_B 16384      // 4096*4096 / (128*8)
#define CV_D 128        // 32*4096   / (128*8)
#define CV_U 1024       // 4096*32   / 128
#define CV_BLKS (CV_X + CV_B + CV_D + CV_U)

__device__ __forceinline__ void conv8(const float* __restrict__ s,
                                      __half* __restrict__ d, size_t i) {
    float4 v0 = *(const float4*)(s + i);
    float4 v1 = *(const float4*)(s + i + 4);
    *(__half2*)(d + i)     = __floats2half2_rn(v0.x, v0.y);
    *(__half2*)(d + i + 2) = __floats2half2_rn(v0.z, v0.w);
    *(__half2*)(d + i + 4) = __floats2half2_rn(v1.x, v1.y);
    *(__half2*)(d + i + 6) = __floats2half2_rn(v1.z, v1.w);
}

__global__ __launch_bounds__(128)
void conv_all(const float* __restrict__ x, const float* __restrict__ base_w,
              const float* __restrict__ down_w, const float* __restrict__ up_w) {
    const int blk = blockIdx.x;
    const int tid = threadIdx.x;
    if (blk < CV_X) {
        conv8(x, g_xh, ((size_t)blk * 128 + tid) * 8);
    } else if (blk < CV_X + CV_B) {
        conv8(base_w, g_bh, ((size_t)(blk - CV_X) * 128 + tid) * 8);
    } else if (blk < CV_X + CV_B + CV_D) {
        conv8(down_w, g_dh, ((size_t)(blk - CV_X - CV_B) * 128 + tid) * 8);
    } else {
        int idx = (blk - CV_X - CV_B - CV_D) * 128 + tid;
        int n = idx >> 5, p = idx & 31;
        int e = p >> 2, r = p & 3;
        __half uh = __float2half(up_w[((size_t)e * D_OUT + n) * RANK + r]);
        __half z  = __float2half(0.0f);
        __half* row = g_uB + (size_t)n * 128;
        row[p] = uh; row[32 + p] = uh;
        row[64 + p] = z; row[96 + p] = z;     // zero-pad upper half
    }
}

// ---------------------------------------------------------------------------
// down_mma: t = xh . dh^T  (M=8192, N=32, K=4096) on tensor cores, with the
// adapter-A (tA hi/lo * 2*rw) epilogue fused in.  tA rows are 128-wide with
// zero upper halves (padding for the BK=128 adapter tail).
// ---------------------------------------------------------------------------
#define DBM 128
#define DRST 144
#define D_A_BYTES (DBM * DRST)           // 18432
#define D_B_BYTES (P32 * DRST)           // 4608
#define D_STAGE (D_A_BYTES + D_B_BYTES)  // 23040
#define D_NSTG 3
#define D_SMEM (D_NSTG * D_STAGE)        // 69120
#define D_NST 64

__device__ __forceinline__ void load_dstage(int s, int buf, int m0, int tid,
                                            uint32_t smbase) {
    const int k0 = s * 64;
    const uint32_t sb = smbase + buf * D_STAGE;
#pragma unroll
    for (int j = 0; j < 8; j++) {
        int c = j * 128 + tid;
        int row = c >> 3, ch = c & 7;
        const __half* g = g_xh + (size_t)(m0 + row) * D_IN + k0 + ch * 8;
        CP_ASYNC16(sb + row * DRST + ch * 16, g);
    }
#pragma unroll
    for (int j = 0; j < 2; j++) {
        int c = j * 128 + tid;
        int row = c >> 3, ch = c & 7;
        const __half* g = g_dh + (size_t)row * D_IN + k0 + ch * 8;
        CP_ASYNC16(sb + D_A_BYTES + row * DRST + ch * 16, g);
    }
}

__global__ __launch_bounds__(128)
void down_mma(const float* __restrict__ rw) {
    extern __shared__ char smem[];
    const uint32_t smbase = smem_u32(smem);
    const int tid  = threadIdx.x;
    const int wid  = tid >> 5;
    const int lane = tid & 31;
    const int m0   = blockIdx.x * DBM;

    float c[2][4][4];
#pragma unroll
    for (int i = 0; i < 2; i++)
#pragma unroll
        for (int j = 0; j < 4; j++)
#pragma unroll
            for (int q = 0; q < 4; q++) c[i][j][q] = 0.0f;

    const uint32_t lm_off = (lane & 15) * DRST + (lane >> 4) * 16;
    const uint32_t a_lane = smbase + (wid * 32) * DRST + lm_off;
    const uint32_t b_lane = smbase + D_A_BYTES + lm_off;

    load_dstage(0, 0, m0, tid, smbase); CP_COMMIT();
    load_dstage(1, 1, m0, tid, smbase); CP_COMMIT();

    int buf = 0, bufp = 2;
    for (int s = 0; s < D_NST; s++) {
        CP_WAIT1();
        __syncthreads();
        if (s + 2 < D_NST)
            load_dstage(s + 2, bufp, m0, tid, smbase);
        CP_COMMIT();

        const uint32_t ab = a_lane + buf * D_STAGE;
        const uint32_t bb = b_lane + buf * D_STAGE;
#pragma unroll
        for (int ks = 0; ks < 4; ks++) {
            uint32_t a[2][4], b[4][2];
            LDSM_X4(b[0][0], b[1][0], b[0][1], b[1][1], bb + ks * 32);
            LDSM_X4(b[2][0], b[3][0], b[2][1], b[3][1], bb + 16 * DRST + ks * 32);
#pragma unroll
            for (int mi = 0; mi < 2; mi++)
                LDSM_X4(a[mi][0], a[mi][1], a[mi][2], a[mi][3],
                        ab + mi * 16 * DRST + ks * 32);
#pragma unroll
            for (int mi = 0; mi < 2; mi++)
#pragma unroll
                for (int ni = 0; ni < 4; ni++)
                    MMA_16816(c[mi][ni], a[mi], b[ni]);
        }
        buf  = (buf  == D_NSTG - 1) ? 0 : buf + 1;
        bufp = (bufp == D_NSTG - 1) ? 0 : bufp + 1;
    }

    // Fused tA epilogue (128-wide rows, zero-padded upper half).
    const __half z = __float2half(0.0f);
#pragma unroll
    for (int mi = 0; mi < 2; mi++) {
        const int r0 = m0 + wid * 32 + mi * 16 + (lane >> 2);
        const int b  = r0 >> 11;
#pragma unroll
        for (int ni = 0; ni < 4; ni++) {
            const int c0 = ni * 8 + 2 * (lane & 3);
            const float s2 = 2.0f * rw[b * NEXP + (c0 >> 2)];
#pragma unroll
            for (int q = 0; q < 4; q++) {
                const int m = (q < 2) ? r0 : r0 + 8;
                const int p = c0 + (q & 1);
                float v = c[mi][ni][q] * s2;
                __half th = __float2half(v);
                __half tl = __float2half(v - __half2float(th));
                __half* row = g_tA + (size_t)m * 128;
                row[p]      = th;
                row[32 + p] = tl;
                row[64 + p] = z;
                row[96 + p] = z;
            }
        }
    }
}

// ---------------------------------------------------------------------------
// Persistent mma.sync GEMM — BK=128, 2-stage pipeline (halves the per-k-tile
// barrier/wait bookkeeping: 33 iterations per tile instead of 65).
// Tile 128(M) x 256(N); warp grid 2x4, warp tile 64x64.  Row stride 272 B
// (272r mod 128 = 16r: same verified 8-bank walk as the 144 B layout).
// K stages per tile: s in [0,32) -> xh.bh (k0 = 128*s) | s=32 -> tail tA.uB
// (tail operands are 128-wide, upper halves zero).
// ---------------------------------------------------------------------------
#define BM 128
#define BN 256
#define BK 128
#define RSTRB 272
#define A_BYTES (BM * RSTRB)             // 34816
#define B_BYTES (BN * RSTRB)             // 69632
#define STAGE_BYTES (A_BYTES + B_BYTES)  // 104448
#define NSTAGES 2
#define SMEM_DYN (NSTAGES * STAGE_BYTES) // 208896
#define NST 33
#define NTILES 1024                      // (4096/256) * (8192/128)
#define GRID_CTAS 148

__device__ __forceinline__ void tile_mn(int bid, int tl, int& m0, int& n0) {
    int t = bid + tl * GRID_CTAS;
    n0 = (t & 15) * BN;
    m0 = (t >> 4) * BM;
}

__device__ __forceinline__ void stage_params(int s, const __half*& ap,
                                             const __half*& bp,
                                             int& ld, int& k0) {
    if (s < 32) { ap = g_xh; bp = g_bh; ld = D_IN; k0 = s * BK; }
    else        { ap = g_tA; bp = g_uB; ld = 128;  k0 = 0; }
}

// Per stage: A = 128 rows x 16 16B-chunks (2048), B = 256 x 16 (4096).
// 6144 chunks / 256 threads = 24 cp.async per thread.
__device__ __forceinline__ void load_stage(int s, int buf, int m0, int n0,
                                           int tid, uint32_t smbase) {
    const __half *ap, *bp;
    int ld, k0;
    stage_params(s, ap, bp, ld, k0);
    const uint32_t sb = smbase + buf * STAGE_BYTES;
#pragma unroll
    for (int j = 0; j < 8; j++) {            // A chunks
        int c = j * 256 + tid;
        int row = c >> 4, ch = c & 15;
        const __half* g = ap + (size_t)(m0 + row) * ld + k0 + ch * 8;
        CP_ASYNC16(sb + row * RSTRB + ch * 16, g);
    }
#pragma unroll
    for (int j = 0; j < 16; j++) {           // B chunks
        int c = j * 256 + tid;
        int row = c >> 4, ch = c & 15;
        const __half* g = bp + (size_t)(n0 + row) * ld + k0 + ch * 8;
        CP_ASYNC16(sb + A_BYTES + row * RSTRB + ch * 16, g);
    }
}

__global__ __launch_bounds__(256, 1)
void gemm_mma(float* __restrict__ out) {
    extern __shared__ char smem[];
    const uint32_t smbase = smem_u32(smem);

    const int tid  = threadIdx.x;
    const int wid  = tid >> 5;
    const int lane = tid & 31;
    const int wm   = wid >> 2;
    const int wn   = wid & 3;
    const int bid  = blockIdx.x;

    const int nt_local = (NTILES - bid + GRID_CTAS - 1) / GRID_CTAS;
    const int total = nt_local * NST;

    float c[4][8][4];
#pragma unroll
    for (int i = 0; i < 4; i++)
#pragma unroll
        for (int j = 0; j < 8; j++)
#pragma unroll
            for (int q = 0; q < 4; q++) c[i][j][q] = 0.0f;

    const uint32_t lm_off = (lane & 15) * RSTRB + (lane >> 4) * 16;
    const uint32_t a_lane = smbase + (wm * 64) * RSTRB + lm_off;
    const uint32_t b_lane = smbase + A_BYTES + (wn * 64) * RSTRB + lm_off;

    // Prefetch cursor / compute cursor
    int pf_s = 0, pf_tl = 0, pf_m0, pf_n0;
    tile_mn(bid, 0, pf_m0, pf_n0);
    int cur_s = 0, cur_tl = 0, cur_m0, cur_n0;
    tile_mn(bid, 0, cur_m0, cur_n0);

    // Prologue: fill 1 stage
    load_stage(pf_s, 0, pf_m0, pf_n0, tid, smbase);
    CP_COMMIT();
    if (++pf_s == NST) {
        pf_s = 0;
        if (++pf_tl < nt_local) tile_mn(bid, pf_tl, pf_m0, pf_n0);
    }

    for (int it = 0; it < total; it++) {
        const int buf = it & 1;
        CP_WAIT0();                 // one stage in flight; compute covers latency
        __syncthreads();

        if (it + 1 < total) {
            load_stage(pf_s, buf ^ 1, pf_m0, pf_n0, tid, smbase);
            if (++pf_s == NST) {
                pf_s = 0;
                if (++pf_tl < nt_local) tile_mn(bid, pf_tl, pf_m0, pf_n0);
            }
        }
        CP_COMMIT();

        const uint32_t ab = a_lane + buf * STAGE_BYTES;
        const uint32_t bb = b_lane + buf * STAGE_BYTES;
#pragma unroll
        for (int ks = 0; ks < 8; ks++) {
            uint32_t a[4][4], b[8][2];
#pragma unroll
            for (int mi = 0; mi < 4; mi++)
                LDSM_X4(a[mi][0], a[mi][1], a[mi][2], a[mi][3],
                        ab + mi * 16 * RSTRB + ks * 32);
#pragma unroll
            for (int nt = 0; nt < 4; nt++)
                LDSM_X4(b[2 * nt][0], b[2 * nt + 1][0],
                        b[2 * nt][1], b[2 * nt + 1][1],
                        bb + nt * 16 * RSTRB + ks * 32);
#pragma unroll
            for (int mi = 0; mi < 4; mi++)
#pragma unroll
                for (int ni = 0; ni < 8; ni++)
                    MMA_16816(c[mi][ni], a[mi], b[ni]);
        }

        if (cur_s == NST - 1) {
            // Tile epilogue (overlaps the in-flight prefetch)
            const int rbase = cur_m0 + wm * 64 + (lane >> 2);
            const int cbase = cur_n0 + wn * 64 + 2 * (lane & 3);
#pragma unroll
            for (int mi = 0; mi < 4; mi++) {
#pragma unroll
                for (int ni = 0; ni < 8; ni++) {
                    float* p0 = out + (size_t)(rbase + mi * 16) * D_OUT + cbase + ni * 8;
                    float* p1 = p0 + 8 * D_OUT;
                    *(float2*)p0 = make_float2(c[mi][ni][0], c[mi][ni][1]);
                    *(float2*)p1 = make_float2(c[mi][ni][2], c[mi][ni][3]);
                }
            }
#pragma unroll
            for (int i = 0; i < 4; i++)
#pragma unroll
                for (int j = 0; j < 8; j++)
#pragma unroll
                    for (int q = 0; q < 4; q++) c[i][j][q] = 0.0f;
            cur_s = 0;
            if (++cur_tl < nt_local) tile_mn(bid, cur_tl, cur_m0, cur_n0);
        } else {
            cur_s++;
        }
    }
}

// ---------------------------------------------------------------------------
// Launch (serial; overlap was measured to regress).
// Inputs (metadata order): x, routing_weights, base_w, down_w, up_w
// ---------------------------------------------------------------------------
extern "C" void kernel_launch(void* const* d_in, const int* in_sizes, int n_in,
                              void* d_out, int out_size) {
    const float* x      = (const float*)d_in[0];
    const float* rw     = (const float*)d_in[1];
    const float* base_w = (const float*)d_in[2];
    const float* down_w = (const float*)d_in[3];
    const float* up_w   = (const float*)d_in[4];
    float* out = (float*)d_out;

    cudaFuncSetAttribute(gemm_mma, cudaFuncAttributeMaxDynamicSharedMemorySize,
                         SMEM_DYN);
    cudaFuncSetAttribute(down_mma, cudaFuncAttributeMaxDynamicSharedMemorySize,
                         D_SMEM);

    conv_all<<<CV_BLKS, 128>>>(x, base_w, down_w, up_w);
    down_mma<<<M_TOT / DBM, 128, D_SMEM>>>(rw);
    gemm_mma<<<GRID_CTAS, 256, SMEM_DYN>>>(out);
}

// round 17
// speedup vs baseline: 1.0321x; 1.0040x over previous
#include <cuda_runtime.h>
#include <cuda_fp16.h>
#include <cstdint>

// ---------------------------------------------------------------------------
// Problem constants
// ---------------------------------------------------------------------------
#define D_IN   4096
#define D_OUT  4096
#define M_TOT  8192
#define NEXP   8
#define RANK   4
#define P32    32

// ---------------------------------------------------------------------------
// Device scratch (static; no cudaMalloc allowed)
// ---------------------------------------------------------------------------
__device__ __half g_xh[(size_t)M_TOT * D_IN];   // fp16 of x
__device__ __half g_bh[(size_t)D_OUT * D_IN];   // fp16 of base_w
__device__ __half g_dh[(size_t)P32 * D_IN];     // fp16 of down_w (as [32, 4096])
__device__ __half g_tA[(size_t)M_TOT * 64];     // [th(32) | tl(32)] * 2*rw
__device__ __half g_uB[(size_t)D_OUT * 64];     // [uh(32) | uh(32)]

// ---------------------------------------------------------------------------
// Helpers
// ---------------------------------------------------------------------------
__device__ __forceinline__ uint32_t smem_u32(const void* p) {
    uint32_t a;
    asm("{ .reg .u64 t; cvta.to.shared.u64 t, %1; cvt.u32.u64 %0, t; }"
        : "=r"(a) : "l"(p));
    return a;
}
#define CP_ASYNC16(so, g) \
    asm volatile("cp.async.cg.shared.global [%0], [%1], 16;" :: "r"(so), "l"(g))
#define CP_COMMIT() asm volatile("cp.async.commit_group;" ::: "memory")
#define CP_WAIT1()  asm volatile("cp.async.wait_group 1;" ::: "memory")
#define CP_WAIT2()  asm volatile("cp.async.wait_group 2;" ::: "memory")

#define LDSM_X4(r0, r1, r2, r3, addr)                                          \
    asm volatile("ldmatrix.sync.aligned.m8n8.x4.shared.b16 {%0,%1,%2,%3}, [%4];"\
                 : "=r"(r0), "=r"(r1), "=r"(r2), "=r"(r3) : "r"(addr))

#define MMA_16816(c, a, b)                                                     \
    asm volatile("mma.sync.aligned.m16n8k16.row.col.f32.f16.f16.f32 "          \
                 "{%0,%1,%2,%3}, {%4,%5,%6,%7}, {%8,%9}, {%0,%1,%2,%3};"       \
                 : "+f"((c)[0]), "+f"((c)[1]), "+f"((c)[2]), "+f"((c)[3])      \
                 : "r"((a)[0]), "r"((a)[1]), "r"((a)[2]), "r"((a)[3]),         \
                   "r"((b)[0]), "r"((b)[1]))

// ---------------------------------------------------------------------------
// conv_all: ONE streaming launch, all DRAM-bound prep (serial with the rest;
// overlapping memory-bound phases was measured to regress).
// ---------------------------------------------------------------------------
#define CV_X 32768      // 8192*4096 / (128*8)
#define CV_B 16384      // 4096*4096 / (128*8)
#define CV_D 128        // 32*4096   / (128*8)
#define CV_U 1024       // 4096*32   / 128
#define CV_BLKS (CV_X + CV_B + CV_D + CV_U)

__device__ __forceinline__ void conv8(const float* __restrict__ s,
                                      __half* __restrict__ d, size_t i) {
    float4 v0 = *(const float4*)(s + i);
    float4 v1 = *(const float4*)(s + i + 4);
    *(__half2*)(d + i)     = __floats2half2_rn(v0.x, v0.y);
    *(__half2*)(d + i + 2) = __floats2half2_rn(v0.z, v0.w);
    *(__half2*)(d + i + 4) = __floats2half2_rn(v1.x, v1.y);
    *(__half2*)(d + i + 6) = __floats2half2_rn(v1.z, v1.w);
}

__global__ __launch_bounds__(128)
void conv_all(const float* __restrict__ x, const float* __restrict__ base_w,
              const float* __restrict__ down_w, const float* __restrict__ up_w) {
    const int blk = blockIdx.x;
    const int tid = threadIdx.x;
    if (blk < CV_X) {
        conv8(x, g_xh, ((size_t)blk * 128 + tid) * 8);
    } else if (blk < CV_X + CV_B) {
        conv8(base_w, g_bh, ((size_t)(blk - CV_X) * 128 + tid) * 8);
    } else if (blk < CV_X + CV_B + CV_D) {
        conv8(down_w, g_dh, ((size_t)(blk - CV_X - CV_B) * 128 + tid) * 8);
    } else {
        int idx = (blk - CV_X - CV_B - CV_D) * 128 + tid;
        int n = idx >> 5, p = idx & 31;
        int e = p >> 2, r = p & 3;
        __half uh = __float2half(up_w[((size_t)e * D_OUT + n) * RANK + r]);
        __half* row = g_uB + (size_t)n * 64;
        row[p] = uh; row[32 + p] = uh;
    }
}

// ---------------------------------------------------------------------------
// down_mma: t = xh . dh^T  (M=8192, N=32, K=4096) on tensor cores, with the
// adapter-A (tA hi/lo * 2*rw) epilogue fused in.  (unchanged from R13)
// ---------------------------------------------------------------------------
#define DBM 128
#define DRST 144
#define D_A_BYTES (DBM * DRST)           // 18432
#define D_B_BYTES (P32 * DRST)           // 4608
#define D_STAGE (D_A_BYTES + D_B_BYTES)  // 23040
#define D_NSTG 3
#define D_SMEM (D_NSTG * D_STAGE)        // 69120
#define D_NST 64

__device__ __forceinline__ void load_dstage(int s, int buf, int m0, int tid,
                                            uint32_t smbase) {
    const int k0 = s * 64;
    const uint32_t sb = smbase + buf * D_STAGE;
#pragma unroll
    for (int j = 0; j < 8; j++) {
        int c = j * 128 + tid;
        int row = c >> 3, ch = c & 7;
        const __half* g = g_xh + (size_t)(m0 + row) * D_IN + k0 + ch * 8;
        CP_ASYNC16(sb + row * DRST + ch * 16, g);
    }
#pragma unroll
    for (int j = 0; j < 2; j++) {
        int c = j * 128 + tid;
        int row = c >> 3, ch = c & 7;
        const __half* g = g_dh + (size_t)row * D_IN + k0 + ch * 8;
        CP_ASYNC16(sb + D_A_BYTES + row * DRST + ch * 16, g);
    }
}

__global__ __launch_bounds__(128)
void down_mma(const float* __restrict__ rw) {
    extern __shared__ char smem[];
    const uint32_t smbase = smem_u32(smem);
    const int tid  = threadIdx.x;
    const int wid  = tid >> 5;
    const int lane = tid & 31;
    const int m0   = blockIdx.x * DBM;

    float c[2][4][4];
#pragma unroll
    for (int i = 0; i < 2; i++)
#pragma unroll
        for (int j = 0; j < 4; j++)
#pragma unroll
            for (int q = 0; q < 4; q++) c[i][j][q] = 0.0f;

    const uint32_t lm_off = (lane & 15) * DRST + (lane >> 4) * 16;
    const uint32_t a_lane = smbase + (wid * 32) * DRST + lm_off;
    const uint32_t b_lane = smbase + D_A_BYTES + lm_off;

    load_dstage(0, 0, m0, tid, smbase); CP_COMMIT();
    load_dstage(1, 1, m0, tid, smbase); CP_COMMIT();

    int buf = 0, bufp = 2;
    for (int s = 0; s < D_NST; s++) {
        CP_WAIT1();
        __syncthreads();
        if (s + 2 < D_NST)
            load_dstage(s + 2, bufp, m0, tid, smbase);
        CP_COMMIT();

        const uint32_t ab = a_lane + buf * D_STAGE;
        const uint32_t bb = b_lane + buf * D_STAGE;
#pragma unroll
        for (int ks = 0; ks < 4; ks++) {
            uint32_t a[2][4], b[4][2];
            LDSM_X4(b[0][0], b[1][0], b[0][1], b[1][1], bb + ks * 32);
            LDSM_X4(b[2][0], b[3][0], b[2][1], b[3][1], bb + 16 * DRST + ks * 32);
#pragma unroll
            for (int mi = 0; mi < 2; mi++)
                LDSM_X4(a[mi][0], a[mi][1], a[mi][2], a[mi][3],
                        ab + mi * 16 * DRST + ks * 32);
#pragma unroll
            for (int mi = 0; mi < 2; mi++)
#pragma unroll
                for (int ni = 0; ni < 4; ni++)
                    MMA_16816(c[mi][ni], a[mi], b[ni]);
        }
        buf  = (buf  == D_NSTG - 1) ? 0 : buf + 1;
        bufp = (bufp == D_NSTG - 1) ? 0 : bufp + 1;
    }

#pragma unroll
    for (int mi = 0; mi < 2; mi++) {
        const int r0 = m0 + wid * 32 + mi * 16 + (lane >> 2);
        const int b  = r0 >> 11;
#pragma unroll
        for (int ni = 0; ni < 4; ni++) {
            const int c0 = ni * 8 + 2 * (lane & 3);
            const float s2 = 2.0f * rw[b * NEXP + (c0 >> 2)];
#pragma unroll
            for (int q = 0; q < 4; q++) {
                const int m = (q < 2) ? r0 : r0 + 8;
                const int p = c0 + (q & 1);
                float v = c[mi][ni][q] * s2;
                __half th = __float2half(v);
                __half tl = __float2half(v - __half2float(th));
                g_tA[(size_t)m * 64 + p]      = th;
                g_tA[(size_t)m * 64 + 32 + p] = tl;
            }
        }
    }
}

// ---------------------------------------------------------------------------
// Persistent mma.sync GEMM — R13 configuration + fragment software pipelining:
// the ldmatrix batch for ks+1 issues BEFORE the MMAs of ks, so the 32
// independent MMAs cover the in-flight LDS latency (double-buffered frags).
// Tile 128(M) x 256(N), BK=64, 4-stage pipeline, warp grid 2x4 (64x64/warp).
// smem rows: 144 B stride; K stages per tile: [0,64) xh.bh | 64: tail tA.uB
// ---------------------------------------------------------------------------
#define BM 128
#define BN 256
#define BK 64
#define RSTRB 144
#define A_BYTES (BM * RSTRB)             // 18432
#define B_BYTES (BN * RSTRB)             // 36864
#define STAGE_BYTES (A_BYTES + B_BYTES)  // 55296
#define NSTAGES 4
#define SMEM_DYN (NSTAGES * STAGE_BYTES) // 221184
#define NST 65
#define NTILES 1024
#define GRID_CTAS 148

__device__ __forceinline__ void tile_mn(int bid, int tl, int& m0, int& n0) {
    int t = bid + tl * GRID_CTAS;
    n0 = (t & 15) * BN;
    m0 = (t >> 4) * BM;
}

__device__ __forceinline__ void stage_params(int s, const __half*& ap,
                                             const __half*& bp,
                                             int& ld, int& k0) {
    if (s < 64) { ap = g_xh; bp = g_bh; ld = D_IN; k0 = s * BK; }
    else        { ap = g_tA; bp = g_uB; ld = 64;   k0 = 0; }
}

__device__ __forceinline__ void load_stage(int s, int buf, int m0, int n0,
                                           int tid, uint32_t smbase) {
    const __half *ap, *bp;
    int ld, k0;
    stage_params(s, ap, bp, ld, k0);
    const uint32_t sb = smbase + buf * STAGE_BYTES;
#pragma unroll
    for (int j = 0; j < 4; j++) {
        int c = j * 256 + tid;
        int row = c >> 3, ch = c & 7;
        const __half* g = ap + (size_t)(m0 + row) * ld + k0 + ch * 8;
        CP_ASYNC16(sb + row * RSTRB + ch * 16, g);
    }
#pragma unroll
    for (int j = 0; j < 8; j++) {
        int c = j * 256 + tid;
        int row = c >> 3, ch = c & 7;
        const __half* g = bp + (size_t)(n0 + row) * ld + k0 + ch * 8;
        CP_ASYNC16(sb + A_BYTES + row * RSTRB + ch * 16, g);
    }
}

// Load one ks-step's fragment set (12 ldmatrix) into register set `set`.
#define LOAD_FRAGS(set, ab, bb, ks)                                            \
    do {                                                                       \
        _Pragma("unroll")                                                      \
        for (int mi = 0; mi < 4; mi++)                                         \
            LDSM_X4(af[set][mi][0], af[set][mi][1],                            \
                    af[set][mi][2], af[set][mi][3],                            \
                    (ab) + mi * 16 * RSTRB + (ks) * 32);                       \
        _Pragma("unroll")                                                      \
        for (int nt = 0; nt < 4; nt++)                                         \
            LDSM_X4(bf[set][2 * nt][0], bf[set][2 * nt + 1][0],                \
                    bf[set][2 * nt][1], bf[set][2 * nt + 1][1],                \
                    (bb) + nt * 16 * RSTRB + (ks) * 32);                       \
    } while (0)

__global__ __launch_bounds__(256, 1)
void gemm_mma(float* __restrict__ out) {
    extern __shared__ char smem[];
    const uint32_t smbase = smem_u32(smem);

    const int tid  = threadIdx.x;
    const int wid  = tid >> 5;
    const int lane = tid & 31;
    const int wm   = wid >> 2;
    const int wn   = wid & 3;
    const int bid  = blockIdx.x;

    const int nt_local = (NTILES - bid + GRID_CTAS - 1) / GRID_CTAS;
    const int total = nt_local * NST;

    float c[4][8][4];
#pragma unroll
    for (int i = 0; i < 4; i++)
#pragma unroll
        for (int j = 0; j < 8; j++)
#pragma unroll
            for (int q = 0; q < 4; q++) c[i][j][q] = 0.0f;

    const uint32_t lm_off = (lane & 15) * RSTRB + (lane >> 4) * 16;
    const uint32_t a_lane = smbase + (wm * 64) * RSTRB + lm_off;
    const uint32_t b_lane = smbase + A_BYTES + (wn * 64) * RSTRB + lm_off;

    int pf_s = 0, pf_tl = 0, pf_m0, pf_n0;
    tile_mn(bid, 0, pf_m0, pf_n0);
    int cur_s = 0, cur_tl = 0, cur_m0, cur_n0;
    tile_mn(bid, 0, cur_m0, cur_n0);

#pragma unroll
    for (int i = 0; i < NSTAGES - 1; i++) {
        load_stage(pf_s, i, pf_m0, pf_n0, tid, smbase);
        CP_COMMIT();
        if (++pf_s == NST) {
            pf_s = 0;
            if (++pf_tl < nt_local) tile_mn(bid, pf_tl, pf_m0, pf_n0);
        }
    }

    uint32_t af[2][4][4], bf[2][8][2];   // double-buffered fragment sets

    int buf = 0, bufp = NSTAGES - 1;
    for (int it = 0; it < total; it++) {
        CP_WAIT2();
        __syncthreads();

        if (it + NSTAGES - 1 < total) {
            load_stage(pf_s, bufp, pf_m0, pf_n0, tid, smbase);
            if (++pf_s == NST) {
                pf_s = 0;
                if (++pf_tl < nt_local) tile_mn(bid, pf_tl, pf_m0, pf_n0);
            }
        }
        CP_COMMIT();

        const uint32_t ab = a_lane + buf * STAGE_BYTES;
        const uint32_t bb = b_lane + buf * STAGE_BYTES;

        // Software-pipelined fragment loop: LDSMs of ks+1 issue before the
        // MMAs of ks; scoreboarding lets the MMAs cover the LDS latency.
        LOAD_FRAGS(0, ab, bb, 0);
#pragma unroll
        for (int ks = 0; ks < 4; ks++) {
            const int cs = ks & 1;
            if (ks < 3) LOAD_FRAGS(cs ^ 1, ab, bb, ks + 1);
#pragma unroll
            for (int mi = 0; mi < 4; mi++)
#pragma unroll
                for (int ni = 0; ni < 8; ni++)
                    MMA_16816(c[mi][ni], af[cs][mi], bf[cs][ni]);
        }

        if (cur_s == NST - 1) {
            const int rbase = cur_m0 + wm * 64 + (lane >> 2);
            const int cbase = cur_n0 + wn * 64 + 2 * (lane & 3);
#pragma unroll
            for (int mi = 0; mi < 4; mi++) {
#pragma unroll
                for (int ni = 0; ni < 8; ni++) {
                    float* p0 = out + (size_t)(rbase + mi * 16) * D_OUT + cbase + ni * 8;
                    float* p1 = p0 + 8 * D_OUT;
                    *(float2*)p0 = make_float2(c[mi][ni][0], c[mi][ni][1]);
                    *(float2*)p1 = make_float2(c[mi][ni][2], c[mi][ni][3]);
                }
            }
#pragma unroll
            for (int i = 0; i < 4; i++)
#pragma unroll
                for (int j = 0; j < 8; j++)
#pragma unroll
                    for (int q = 0; q < 4; q++) c[i][j][q] = 0.0f;
            cur_s = 0;
            if (++cur_tl < nt_local) tile_mn(bid, cur_tl, cur_m0, cur_n0);
        } else {
            cur_s++;
        }

        buf  = (buf  == NSTAGES - 1) ? 0 : buf + 1;
        bufp = (bufp == NSTAGES - 1) ? 0 : bufp + 1;
    }
}

// ---------------------------------------------------------------------------
// Launch (serial; overlap was measured to regress).
// Inputs (metadata order): x, routing_weights, base_w, down_w, up_w
// ---------------------------------------------------------------------------
extern "C" void kernel_launch(void* const* d_in, const int* in_sizes, int n_in,
                              void* d_out, int out_size) {
    const float* x      = (const float*)d_in[0];
    const float* rw     = (const float*)d_in[1];
    const float* base_w = (const float*)d_in[2];
    const float* down_w = (const float*)d_in[3];
    const float* up_w   = (const float*)d_in[4];
    float* out = (float*)d_out;

    cudaFuncSetAttribute(gemm_mma, cudaFuncAttributeMaxDynamicSharedMemorySize,
                         SMEM_DYN);
    cudaFuncSetAttribute(down_mma, cudaFuncAttributeMaxDynamicSharedMemorySize,
                         D_SMEM);

    conv_all<<<CV_BLKS, 128>>>(x, base_w, down_w, up_w);
    down_mma<<<M_TOT / DBM, 128, D_SMEM>>>(rw);
    gemm_mma<<<GRID_CTAS, 256, SMEM_DYN>>>(out);
}